// round 9
// baseline (speedup 1.0000x reference)
#include <cuda_runtime.h>

#define NBODY  63
#define NHINGE 61
#define NSITES 16
#define QDIM   68   // 7 free-joint + 61 hinge
#define BLK    128
#define EPB    256  // elements per block (2 per thread)
#define OPAD   49   // padded output row (floats); gcd(49,32)=1 -> conflict-free STS

// dynamic smem layout (bytes):
//   5*61*16 = 4880   Q1,Q2,VC,F1,F2
//   16*16   = 256    SP
//   64*4    = 256    mask (padded to 64)
//   256*49*4 = 50176 sOut
#define SMEM_TOTAL (4880 + 256 + 256 + EPB * OPAD * 4)

// Per-hinge folded constants + site metadata, produced by fk_init each launch.
struct FKConst {
    float4 Q1[NHINGE];        // body_quat[bid]              (w,x,y,z)
    float4 Q2[NHINGE];        // qmul(body_quat[bid],(0,ax)) (w,x,y,z)
    float4 VC[NHINGE];        // body_pos + jnt_pos - f0
    float4 F1[NHINGE];        // R(Q1)(j - ax(ax.j))
    float4 F2[NHINGE];        // R(Q1)(ax x j)
    float4 SP[NSITES];        // site_pos
    unsigned int mask[NBODY]; // bitmask of sites attached to each body
};
__device__ FKConst g_fk;

__global__ void fk_init(const float* __restrict__ body_pos,
                        const float* __restrict__ body_quat,
                        const float* __restrict__ hinge_axis,
                        const float* __restrict__ jnt_pos,
                        const float* __restrict__ site_pos,
                        const int*   __restrict__ site_body) {
    int t = threadIdx.x;
    if (t < NBODY) g_fk.mask[t] = 0u;
    if (t < NHINGE) {
        int bid = t + 2;
        float w1 = body_quat[bid*4+0], x1 = body_quat[bid*4+1];
        float y1 = body_quat[bid*4+2], z1 = body_quat[bid*4+3];
        float ax = hinge_axis[t*3+0], ay = hinge_axis[t*3+1], az = hinge_axis[t*3+2];
        g_fk.Q1[t] = make_float4(w1, x1, y1, z1);
        g_fk.Q2[t] = make_float4(-x1*ax - y1*ay - z1*az,
                                  w1*ax + y1*az - z1*ay,
                                  w1*ay - x1*az + z1*ax,
                                  w1*az + x1*ay - y1*ax);
        float jx = jnt_pos[t*3+0], jy = jnt_pos[t*3+1], jz = jnt_pos[t*3+2];
        // Rodrigues: R(ax,theta) j = e0 + cosT*e1 + sinT*e2
        float d = ax*jx + ay*jy + az*jz;
        float e0x = ax*d, e0y = ay*d, e0z = az*d;
        float e1x = jx - e0x, e1y = jy - e0y, e1z = jz - e0z;
        float e2x = ay*jz - az*jy, e2y = az*jx - ax*jz, e2z = ax*jy - ay*jx;
        auto qrot = [&](float vx, float vy, float vz, float& ox, float& oy, float& oz) {
            float tx = 2.f*(y1*vz - z1*vy);
            float ty = 2.f*(z1*vx - x1*vz);
            float tz = 2.f*(x1*vy - y1*vx);
            ox = vx + w1*tx + (y1*tz - z1*ty);
            oy = vy + w1*ty + (z1*tx - x1*tz);
            oz = vz + w1*tz + (x1*ty - y1*tx);
        };
        float f0x,f0y,f0z, f1x,f1y,f1z, f2x,f2y,f2z;
        qrot(e0x,e0y,e0z, f0x,f0y,f0z);
        qrot(e1x,e1y,e1z, f1x,f1y,f1z);
        qrot(e2x,e2y,e2z, f2x,f2y,f2z);
        g_fk.VC[t] = make_float4(body_pos[bid*3+0] + jx - f0x,
                                 body_pos[bid*3+1] + jy - f0y,
                                 body_pos[bid*3+2] + jz - f0z, 0.f);
        g_fk.F1[t] = make_float4(f1x, f1y, f1z, 0.f);
        g_fk.F2[t] = make_float4(f2x, f2y, f2z, 0.f);
    }
    if (t < NSITES)
        g_fk.SP[t] = make_float4(site_pos[t*3+0], site_pos[t*3+1], site_pos[t*3+2], 0.f);
    __syncthreads();
    if (t < NSITES)
        atomicOr(&g_fk.mask[site_body[t]], 1u << t);
}

__global__ __launch_bounds__(BLK, 4)
void fk_main(const float* __restrict__ qpos, float* __restrict__ out, int B) {
    extern __shared__ __align__(16) float dyn[];
    float4* sQ1 = (float4*)dyn;
    float4* sQ2 = sQ1 + NHINGE;
    float4* sVC = sQ2 + NHINGE;
    float4* sF1 = sVC + NHINGE;
    float4* sF2 = sF1 + NHINGE;
    float4* sSP = sF2 + NHINGE;
    unsigned int* sMask = (unsigned int*)(sSP + NSITES);
    float* sOut = (float*)(sMask + 64);

    const int tid = threadIdx.x;
    for (int i = tid; i < NHINGE; i += BLK) {
        sQ1[i] = g_fk.Q1[i]; sQ2[i] = g_fk.Q2[i];
        sVC[i] = g_fk.VC[i]; sF1[i] = g_fk.F1[i]; sF2[i] = g_fk.F2[i];
    }
    if (tid < NSITES) sSP[tid] = g_fk.SP[tid];
    if (tid < NBODY)  sMask[tid] = g_fk.mask[tid];
    __syncthreads();

    const int base  = blockIdx.x * EPB;
    const int nElem = (B - base < EPB) ? (B - base) : EPB;

    {
        // Two chains per thread; clamp indices so partial blocks stay in-bounds
        // (rows beyond nElem are computed but never stored).
        int b0 = base + tid;           if (b0 >= B) b0 = B - 1;
        int b1 = base + tid + BLK;     if (b1 >= B) b1 = B - 1;
        const float4* q4a = (const float4*)(qpos + (size_t)b0 * QDIM);
        const float4* q4b = (const float4*)(qpos + (size_t)b1 * QDIM);
        float* soa = sOut + tid * OPAD;
        float* sob = sOut + (tid + BLK) * OPAD;

        float4 fa0 = q4a[0], fa1 = q4a[1];
        float4 fb0 = q4b[0], fb1 = q4b[1];

        float wpx0 = fa0.x, wpy0 = fa0.y, wpz0 = fa0.z;
        float qw0 = fa0.w, qx0 = fa1.x, qy0 = fa1.y, qz0 = fa1.z;
        float rn0 = rsqrtf(qw0*qw0 + qx0*qx0 + qy0*qy0 + qz0*qz0);
        qw0 *= rn0; qx0 *= rn0; qy0 *= rn0; qz0 *= rn0;

        float wpx1 = fb0.x, wpy1 = fb0.y, wpz1 = fb0.z;
        float qw1 = fb0.w, qx1 = fb1.x, qy1 = fb1.y, qz1 = fb1.z;
        float rn1 = rsqrtf(qw1*qw1 + qx1*qx1 + qy1*qy1 + qz1*qz1);
        qw1 *= rn1; qx1 *= rn1; qy1 *= rn1; qz1 *= rn1;

        // Emit one site for both chains
        auto emit = [&](int s, float4 sp) {
            float ux0 = 2.f*(qy0*sp.z - qz0*sp.y);
            float uy0 = 2.f*(qz0*sp.x - qx0*sp.z);
            float uz0 = 2.f*(qx0*sp.y - qy0*sp.x);
            soa[s*3+0] = wpx0 + sp.x + qw0*ux0 + (qy0*uz0 - qz0*uy0);
            soa[s*3+1] = wpy0 + sp.y + qw0*uy0 + (qz0*ux0 - qx0*uz0);
            soa[s*3+2] = wpz0 + sp.z + qw0*uz0 + (qx0*uy0 - qy0*ux0);
            float ux1 = 2.f*(qy1*sp.z - qz1*sp.y);
            float uy1 = 2.f*(qz1*sp.x - qx1*sp.z);
            float uz1 = 2.f*(qx1*sp.y - qy1*sp.x);
            sob[s*3+0] = wpx1 + sp.x + qw1*ux1 + (qy1*uz1 - qz1*uy1);
            sob[s*3+1] = wpy1 + sp.y + qw1*uy1 + (qz1*ux1 - qx1*uz1);
            sob[s*3+2] = wpz1 + sp.z + qw1*uz1 + (qx1*uy1 - qy1*ux1);
        };

        unsigned int m1 = sMask[1];
        while (m1) {
            int s = __ffs(m1) - 1; m1 &= m1 - 1;
            emit(s, sSP[s]);
        }

        // One hinge step for both chains; half-angle sincos precomputed.
        auto step = [&](int h, float sn0, float cs0, float sn1, float cs1) {
            float4 Q1 = sQ1[h], Q2 = sQ2[h];
            float4 Vc = sVC[h], F1 = sF1[h], F2 = sF2[h];

            // ---- chain 0 ----
            {
                float lw = cs0*Q1.x + sn0*Q2.x;
                float lx = cs0*Q1.y + sn0*Q2.y;
                float ly = cs0*Q1.z + sn0*Q2.z;
                float lz = cs0*Q1.w + sn0*Q2.w;
                float nw = qw0*lw - qx0*lx - qy0*ly - qz0*lz;
                float nx = qw0*lx + qx0*lw + qy0*lz - qz0*ly;
                float ny = qw0*ly - qx0*lz + qy0*lw + qz0*lx;
                float nz = qw0*lz + qx0*ly - qy0*lx + qz0*lw;
                float s2   = sn0 + sn0;
                float sinT = s2 * cs0;
                float cosT = fmaf(-sn0, s2, 1.f);
                float gx = Vc.x - cosT*F1.x - sinT*F2.x;
                float gy = Vc.y - cosT*F1.y - sinT*F2.y;
                float gz = Vc.z - cosT*F1.z - sinT*F2.z;
                float tx = 2.f*(qy0*gz - qz0*gy);
                float ty = 2.f*(qz0*gx - qx0*gz);
                float tz = 2.f*(qx0*gy - qy0*gx);
                wpx0 += gx + qw0*tx + (qy0*tz - qz0*ty);
                wpy0 += gy + qw0*ty + (qz0*tx - qx0*tz);
                wpz0 += gz + qw0*tz + (qx0*ty - qy0*tx);
                qw0 = nw; qx0 = nx; qy0 = ny; qz0 = nz;
            }
            // ---- chain 1 ----
            {
                float lw = cs1*Q1.x + sn1*Q2.x;
                float lx = cs1*Q1.y + sn1*Q2.y;
                float ly = cs1*Q1.z + sn1*Q2.z;
                float lz = cs1*Q1.w + sn1*Q2.w;
                float nw = qw1*lw - qx1*lx - qy1*ly - qz1*lz;
                float nx = qw1*lx + qx1*lw + qy1*lz - qz1*ly;
                float ny = qw1*ly - qx1*lz + qy1*lw + qz1*lx;
                float nz = qw1*lz + qx1*ly - qy1*lx + qz1*lw;
                float s2   = sn1 + sn1;
                float sinT = s2 * cs1;
                float cosT = fmaf(-sn1, s2, 1.f);
                float gx = Vc.x - cosT*F1.x - sinT*F2.x;
                float gy = Vc.y - cosT*F1.y - sinT*F2.y;
                float gz = Vc.z - cosT*F1.z - sinT*F2.z;
                float tx = 2.f*(qy1*gz - qz1*gy);
                float ty = 2.f*(qz1*gx - qx1*gz);
                float tz = 2.f*(qx1*gy - qy1*gx);
                wpx1 += gx + qw1*tx + (qy1*tz - qz1*ty);
                wpy1 += gy + qw1*ty + (qz1*tx - qx1*tz);
                wpz1 += gz + qw1*tz + (qx1*ty - qy1*tx);
                qw1 = nw; qx1 = nx; qy1 = ny; qz1 = nz;
            }

            unsigned int mm = sMask[h + 2];
            while (mm) {
                int s = __ffs(mm) - 1; mm &= mm - 1;
                emit(s, sSP[s]);
            }
        };

        // h = 0 from lane .w of the second float4, then 15 groups of 4.
        {
            float s0a, c0a, s0b, c0b;
            __sincosf(0.5f * fa1.w, &s0a, &c0a);
            __sincosf(0.5f * fb1.w, &s0b, &c0b);
            step(0, s0a, c0a, s0b, c0b);
        }
        float4 ava = q4a[2];
        float4 avb = q4b[2];
        #pragma unroll 1
        for (int g = 0; g < 15; ++g) {
            float4 ca = ava, cb = avb;
            if (g < 14) { ava = q4a[3 + g]; avb = q4b[3 + g]; }
            float sa0,ca0, sa1,ca1, sa2,ca2, sa3,ca3;
            float sb0,cb0, sb1,cb1, sb2,cb2, sb3,cb3;
            __sincosf(0.5f * ca.x, &sa0, &ca0);
            __sincosf(0.5f * cb.x, &sb0, &cb0);
            __sincosf(0.5f * ca.y, &sa1, &ca1);
            __sincosf(0.5f * cb.y, &sb1, &cb1);
            __sincosf(0.5f * ca.z, &sa2, &ca2);
            __sincosf(0.5f * cb.z, &sb2, &cb2);
            __sincosf(0.5f * ca.w, &sa3, &ca3);
            __sincosf(0.5f * cb.w, &sb3, &cb3);
            step(4*g + 1, sa0, ca0, sb0, cb0);
            step(4*g + 2, sa1, ca1, sb1, cb1);
            step(4*g + 3, sa2, ca2, sb2, cb2);
            step(4*g + 4, sa3, ca3, sb3, cb3);
        }
    }

    __syncthreads();

    // Cooperative coalesced store: gather from padded rows, STG.128 contiguous
    {
        float4* ov = (float4*)(out + (size_t)base * 48);
        int total4 = nElem * 12;   // 12 float4 per element
        for (int i = tid; i < total4; i += BLK) {
            int e = i / 12;
            int j = i - e * 12;
            const float* src = sOut + e * OPAD + j * 4;
            ov[i] = make_float4(src[0], src[1], src[2], src[3]);
        }
    }
}

extern "C" void kernel_launch(void* const* d_in, const int* in_sizes, int n_in,
                              void* d_out, int out_size) {
    const float* qpos       = (const float*)d_in[0];
    const float* body_pos   = (const float*)d_in[1];
    const float* body_quat  = (const float*)d_in[2];
    const float* hinge_axis = (const float*)d_in[3];
    const float* jnt_pos    = (const float*)d_in[4];
    const float* site_pos   = (const float*)d_in[5];
    const int*   site_body  = (const int*)d_in[7];

    int B = in_sizes[0] / QDIM;

    static int attrs_set = 0;
    if (!attrs_set) {
        cudaFuncSetAttribute(fk_main, cudaFuncAttributeMaxDynamicSharedMemorySize, SMEM_TOTAL);
        cudaFuncSetAttribute(fk_main, cudaFuncAttributePreferredSharedMemoryCarveout, 100);
        attrs_set = 1;
    }

    fk_init<<<1, 64>>>(body_pos, body_quat, hinge_axis, jnt_pos, site_pos, site_body);
    fk_main<<<(B + EPB - 1) / EPB, BLK, SMEM_TOTAL>>>(qpos, (float*)d_out, B);
}